// round 1
// baseline (speedup 1.0000x reference)
#include <cuda_runtime.h>
#include <math.h>

// ----------------------------------------------------------------------------
// SelfAttention: B=8, N=2048, D_IN=768, D_OUT=768
//   qkv = x @ W_qkv + b_qkv            (16384 x 2304 x 768)
//   S   = Q K^T * 1/sqrt(768)          (8 x 2048 x 2048 x 768)
//   P   = softmax(S)
//   out = P V                          (8 x 2048 x 768 x 2048)
// All fp32. Scratch in __device__ globals (no allocation).
// ----------------------------------------------------------------------------

#define BATCH   8
#define SEQ     2048
#define DMODEL  768
#define DQKV    2304            // 3 * 768
#define MROWS   (BATCH * SEQ)   // 16384

__device__ float g_qkv[(long long)MROWS * DQKV];          // 151 MB
__device__ float g_scores[(long long)BATCH * SEQ * SEQ];  // 134 MB

// ---------------- tiled fp32 GEMM ----------------
// C[M,N] = A[M,K] * op(B) (+bias | *scale)
//   TRANSB=0: B is [K,N] row-major (ldb = row stride)
//   TRANSB=1: B is [N,K] row-major (C = A B^T)
// All of M,N divisible by 128; K divisible by 16 (true for all 3 calls).
#define BM 128
#define BN 128
#define BK 16
#define TM 8
#define TN 8

#define MODE_BIAS  0
#define MODE_SCALE 1
#define MODE_NONE  2

template<int TRANSB, int MODE>
__global__ __launch_bounds__(256)
void gemm_kernel(const float* __restrict__ A,
                 const float* __restrict__ B,
                 float* __restrict__ C,
                 const float* __restrict__ bias,
                 int M, int N, int K,
                 int lda, int ldb, int ldc,
                 long long strideA, long long strideB, long long strideC,
                 float scale)
{
    __shared__ float As[BK][BM];
    __shared__ float Bs[BK][BN];

    const int bz = blockIdx.z;
    A += (long long)bz * strideA;
    B += (long long)bz * strideB;
    C += (long long)bz * strideC;

    const int tid = threadIdx.x;
    const int tx = tid & 15;          // 0..15  -> column group
    const int ty = tid >> 4;          // 0..15  -> row group
    const int row0 = blockIdx.y * BM;
    const int col0 = blockIdx.x * BN;

    float acc[TM][TN];
#pragma unroll
    for (int i = 0; i < TM; ++i)
#pragma unroll
        for (int j = 0; j < TN; ++j) acc[i][j] = 0.0f;

    for (int k0 = 0; k0 < K; k0 += BK) {
        // --- load A tile: BM x BK, store transposed As[k][m] ---
#pragma unroll
        for (int i = 0; i < 2; ++i) {
            int v  = tid * 2 + i;          // 0..511 float4 slots
            int r  = v >> 2;               // row in tile (4 float4 per row)
            int kq = v & 3;
            const float4 t = *(const float4*)(A + (long long)(row0 + r) * lda + (k0 + kq * 4));
            As[kq * 4 + 0][r] = t.x;
            As[kq * 4 + 1][r] = t.y;
            As[kq * 4 + 2][r] = t.z;
            As[kq * 4 + 3][r] = t.w;
        }
        // --- load B tile into Bs[k][n] ---
        if (TRANSB == 0) {
#pragma unroll
            for (int i = 0; i < 2; ++i) {
                int v  = tid * 2 + i;      // 0..511
                int r  = v >> 5;           // k row (32 float4 per row)
                int nq = v & 31;
                const float4 t = *(const float4*)(B + (long long)(k0 + r) * ldb + (col0 + nq * 4));
                *(float4*)&Bs[r][nq * 4] = t;
            }
        } else {
#pragma unroll
            for (int i = 0; i < 2; ++i) {
                int v  = tid * 2 + i;
                int r  = v >> 2;           // n row in tile
                int kq = v & 3;
                const float4 t = *(const float4*)(B + (long long)(col0 + r) * ldb + (k0 + kq * 4));
                Bs[kq * 4 + 0][r] = t.x;
                Bs[kq * 4 + 1][r] = t.y;
                Bs[kq * 4 + 2][r] = t.z;
                Bs[kq * 4 + 3][r] = t.w;
            }
        }
        __syncthreads();

#pragma unroll
        for (int k = 0; k < BK; ++k) {
            float4 a0 = *(const float4*)&As[k][ty * TM];
            float4 a1 = *(const float4*)&As[k][ty * TM + 4];
            float4 b0 = *(const float4*)&Bs[k][tx * TN];
            float4 b1 = *(const float4*)&Bs[k][tx * TN + 4];
            float a[TM] = {a0.x, a0.y, a0.z, a0.w, a1.x, a1.y, a1.z, a1.w};
            float b[TN] = {b0.x, b0.y, b0.z, b0.w, b1.x, b1.y, b1.z, b1.w};
#pragma unroll
            for (int i = 0; i < TM; ++i)
#pragma unroll
                for (int j = 0; j < TN; ++j)
                    acc[i][j] = fmaf(a[i], b[j], acc[i][j]);
        }
        __syncthreads();
    }

    // --- epilogue ---
    float bj[TN];
    if (MODE == MODE_BIAS) {
#pragma unroll
        for (int j = 0; j < TN; ++j) bj[j] = bias[col0 + tx * TN + j];
    }
#pragma unroll
    for (int i = 0; i < TM; ++i) {
        long long r = row0 + ty * TM + i;
        float* cp = C + r * ldc + (col0 + tx * TN);
        float4 v0, v1;
        float v[TN];
#pragma unroll
        for (int j = 0; j < TN; ++j) {
            float x = acc[i][j];
            if (MODE == MODE_BIAS)  x += bj[j];
            if (MODE == MODE_SCALE) x *= scale;
            v[j] = x;
        }
        v0 = make_float4(v[0], v[1], v[2], v[3]);
        v1 = make_float4(v[4], v[5], v[6], v[7]);
        *(float4*)(cp)     = v0;
        *(float4*)(cp + 4) = v1;
    }
}

// ---------------- row softmax over 2048 cols ----------------
__global__ __launch_bounds__(256)
void softmax_kernel(float* __restrict__ S)
{
    __shared__ float red[32];
    const int NCOL = SEQ;          // 2048
    const int tid = threadIdx.x;   // 256 threads, 8 cols each
    float* p = S + (long long)blockIdx.x * NCOL;

    float v[8];
    float m = -INFINITY;
#pragma unroll
    for (int i = 0; i < 8; ++i) {
        v[i] = p[tid + i * 256];
        m = fmaxf(m, v[i]);
    }
    // block max
#pragma unroll
    for (int o = 16; o; o >>= 1) m = fmaxf(m, __shfl_xor_sync(0xffffffffu, m, o));
    const int warp = tid >> 5, lane = tid & 31;
    if (lane == 0) red[warp] = m;
    __syncthreads();
    if (warp == 0) {
        float t = (lane < 8) ? red[lane] : -INFINITY;
#pragma unroll
        for (int o = 4; o; o >>= 1) t = fmaxf(t, __shfl_xor_sync(0xffffffffu, t, o));
        if (lane == 0) red[0] = t;
    }
    __syncthreads();
    m = red[0];
    __syncthreads();

    float s = 0.0f;
#pragma unroll
    for (int i = 0; i < 8; ++i) {
        v[i] = __expf(v[i] - m);
        s += v[i];
    }
#pragma unroll
    for (int o = 16; o; o >>= 1) s += __shfl_xor_sync(0xffffffffu, s, o);
    if (lane == 0) red[warp] = s;
    __syncthreads();
    if (warp == 0) {
        float t = (lane < 8) ? red[lane] : 0.0f;
#pragma unroll
        for (int o = 4; o; o >>= 1) t += __shfl_xor_sync(0xffffffffu, t, o);
        if (lane == 0) red[0] = t;
    }
    __syncthreads();
    const float inv = 1.0f / red[0];
#pragma unroll
    for (int i = 0; i < 8; ++i) p[tid + i * 256] = v[i] * inv;
}

// ---------------- launch ----------------
extern "C" void kernel_launch(void* const* d_in, const int* in_sizes, int n_in,
                              void* d_out, int out_size)
{
    const float* x = (const float*)d_in[0];   // [8,2048,768]
    const float* W = (const float*)d_in[1];   // [768,2304]
    const float* b = (const float*)d_in[2];   // [2304]
    float* out = (float*)d_out;               // [8,2048,768]

    float* qkv = nullptr;
    float* scores = nullptr;
    cudaGetSymbolAddress((void**)&qkv, g_qkv);
    cudaGetSymbolAddress((void**)&scores, g_scores);

    const float scale = 1.0f / sqrtf((float)DMODEL);
    dim3 blk(256);

    // 1) qkv = x @ W + b : M=16384, N=2304, K=768
    gemm_kernel<0, MODE_BIAS><<<dim3(DQKV / BN, MROWS / BM, 1), blk>>>(
        x, W, qkv, b,
        MROWS, DQKV, DMODEL,
        DMODEL, DQKV, DQKV,
        0LL, 0LL, 0LL, 1.0f);

    // 2) S = Q K^T * scale : per batch M=N=2048, K=768
    gemm_kernel<1, MODE_SCALE><<<dim3(SEQ / BN, SEQ / BM, BATCH), blk>>>(
        qkv + 0, qkv + DMODEL, scores, nullptr,
        SEQ, SEQ, DMODEL,
        DQKV, DQKV, SEQ,
        (long long)SEQ * DQKV, (long long)SEQ * DQKV, (long long)SEQ * SEQ,
        scale);

    // 3) softmax rows
    softmax_kernel<<<BATCH * SEQ, 256>>>(scores);

    // 4) out = P @ V : per batch M=2048, N=768, K=2048
    gemm_kernel<0, MODE_NONE><<<dim3(DMODEL / BN, SEQ / BM, BATCH), blk>>>(
        scores, qkv + 2 * DMODEL, out, nullptr,
        SEQ, DMODEL, SEQ,
        SEQ, DQKV, DMODEL,
        (long long)SEQ * SEQ, (long long)SEQ * DQKV, (long long)SEQ * DMODEL,
        1.0f);
}

// round 4
// speedup vs baseline: 2.2793x; 2.2793x over previous
#include <cuda_runtime.h>
#include <cuda_bf16.h>
#include <math.h>
#include <stdint.h>

// ----------------------------------------------------------------------------
// SelfAttention B=8, N=2048, D=768 — portable-PTX tensor cores (mma.sync bf16,
// fp32 accum) since the build target is plain sm_100 (no tcgen05).
// fp32 operands split ONCE to bf16 hi/lo; GEMMs do AhBh + AhBl + AlBh.
// GEMM: 128x128x32 CTA tile, 8 warps (64x32 each), cp.async 3-stage pipeline.
// ----------------------------------------------------------------------------

#define BATCH   8
#define SEQ     2048
#define DMODEL  768
#define DQKV    2304
#define MROWS   (BATCH * SEQ)

typedef __nv_bfloat16 bf16;

__device__ bf16  g_xh[(long long)MROWS * DMODEL];
__device__ bf16  g_xl[(long long)MROWS * DMODEL];
__device__ bf16  g_wth[(long long)DQKV * DMODEL];        // W^T K-major [2304][768]
__device__ bf16  g_wtl[(long long)DQKV * DMODEL];
__device__ bf16  g_qh[(long long)MROWS * DQKV];
__device__ bf16  g_ql[(long long)MROWS * DQKV];
__device__ float g_scores[(long long)BATCH * SEQ * SEQ];
__device__ bf16  g_ph[(long long)BATCH * SEQ * SEQ];
__device__ bf16  g_pl[(long long)BATCH * SEQ * SEQ];
__device__ bf16  g_vth[(long long)BATCH * DMODEL * SEQ]; // V^T per batch [768][2048]
__device__ bf16  g_vtl[(long long)BATCH * DMODEL * SEQ];

// ------------------------- helpers -------------------------
__device__ __forceinline__ uint32_t smem_u32(const void* p) {
    uint32_t a;
    asm("{ .reg .u64 t; cvta.to.shared.u64 t, %1; cvt.u32.u64 %0, t; }"
        : "=r"(a) : "l"(p));
    return a;
}
__device__ __forceinline__ void split2(float x, bf16& h, bf16& l) {
    h = __float2bfloat16(x);
    l = __float2bfloat16(x - __bfloat162float(h));
}
__device__ __forceinline__ uint32_t pack2(bf16 a, bf16 b) {
    __nv_bfloat162 v(a, b);
    return *reinterpret_cast<uint32_t*>(&v);
}

#define CPA16(dst, src) \
    asm volatile("cp.async.cg.shared.global [%0], [%1], 16;" :: "r"(dst), "l"(src))
#define CPA_COMMIT() asm volatile("cp.async.commit_group;" ::: "memory")
#define CPA_WAIT1()  asm volatile("cp.async.wait_group 1;" ::: "memory")

#define LDSM4(r0, r1, r2, r3, addr) \
    asm volatile("ldmatrix.sync.aligned.m8n8.x4.shared.b16 {%0,%1,%2,%3}, [%4];" \
                 : "=r"(r0), "=r"(r1), "=r"(r2), "=r"(r3) : "r"(addr))

#define MMA16816(d, a, b) \
    asm volatile("mma.sync.aligned.m16n8k16.row.col.f32.bf16.bf16.f32 " \
                 "{%0,%1,%2,%3}, {%4,%5,%6,%7}, {%8,%9}, {%0,%1,%2,%3};" \
                 : "+f"((d)[0]), "+f"((d)[1]), "+f"((d)[2]), "+f"((d)[3]) \
                 : "r"((a)[0]), "r"((a)[1]), "r"((a)[2]), "r"((a)[3]), \
                   "r"((b)[0]), "r"((b)[1]))

// 64B rows, 4x16B chunks; conflict-free swizzle across 8-row ldmatrix phases
#define SWZC(r, c) ((c) ^ (((r) ^ ((r) >> 2)) & 3))

// ------------------------- GEMM config -------------------------
#define BM 128
#define BN 128
#define BKE 32            // bf16 k elems per chunk (64 bytes per row)
#define STAGES 3
#define SM_AH 0
#define SM_AL 8192
#define SM_BH 16384
#define SM_BL 24576
#define SM_STAGE 32768
#define SM_TOTAL (STAGES * SM_STAGE)   // 98304

#define MODE_SPLIT_BIAS 0
#define MODE_SCALE_F32  1
#define MODE_F32        2

template<int MODE>
__global__ __launch_bounds__(256)
void gemm_mma(const bf16* __restrict__ Ah, const bf16* __restrict__ Al,
              const bf16* __restrict__ Bh, const bf16* __restrict__ Bl,
              float* __restrict__ Cf, bf16* __restrict__ Ch, bf16* __restrict__ Cl,
              const float* __restrict__ bias,
              int K, int lda, int ldb, int ldc,
              long long sA, long long sB, long long sC, float scale)
{
    extern __shared__ char smem[];
    const uint32_t sm = smem_u32(smem);
    const int tid  = threadIdx.x;
    const int wid  = tid >> 5;
    const int lane = tid & 31;
    const int wm   = wid & 1;        // 2 warps along M (64 rows each)
    const int wn   = wid >> 1;       // 4 warps along N (32 cols each)
    const int row0 = blockIdx.y * BM;
    const int col0 = blockIdx.x * BN;

    const long long ldaB = (long long)lda * 2;
    const long long ldbB = (long long)ldb * 2;
    const char* pAh = (const char*)(Ah + blockIdx.z * sA + (long long)row0 * lda);
    const char* pAl = (const char*)(Al + blockIdx.z * sA + (long long)row0 * lda);
    const char* pBh = (const char*)(Bh + blockIdx.z * sB + (long long)col0 * ldb);
    const char* pBl = (const char*)(Bl + blockIdx.z * sB + (long long)col0 * ldb);

    float acc[4][4][4];
#pragma unroll
    for (int i = 0; i < 4; ++i)
#pragma unroll
        for (int j = 0; j < 4; ++j)
#pragma unroll
            for (int t = 0; t < 4; ++t) acc[i][j][t] = 0.0f;

    const int NC = K / BKE;

    // thread's 2 copy slots (per array): u = tid*2+i -> row u>>2, chunk u&3
    auto load_chunk = [&](int ch) {
        const uint32_t stb = sm + (ch % STAGES) * SM_STAGE;
        const long long kb = (long long)ch * 64;
#pragma unroll
        for (int i = 0; i < 2; ++i) {
            int u = tid * 2 + i;
            int r = u >> 2, c = u & 3;
            uint32_t dsw = (uint32_t)(r * 64 + (SWZC(r, c) << 4));
            long long goA = (long long)r * ldaB + kb + c * 16;
            long long goB = (long long)r * ldbB + kb + c * 16;
            CPA16(stb + SM_AH + dsw, pAh + goA);
            CPA16(stb + SM_AL + dsw, pAl + goA);
            CPA16(stb + SM_BH + dsw, pBh + goB);
            CPA16(stb + SM_BL + dsw, pBl + goB);
        }
    };

    load_chunk(0); CPA_COMMIT();
    load_chunk(1); CPA_COMMIT();

    const int g  = lane >> 3;
    const int rr = lane & 7;

    for (int ch = 0; ch < NC; ++ch) {
        CPA_WAIT1();
        __syncthreads();
        if (ch + 2 < NC) load_chunk(ch + 2);
        CPA_COMMIT();

        const uint32_t stb = sm + (ch % STAGES) * SM_STAGE;
#pragma unroll
        for (int s = 0; s < 2; ++s) {
            // B fragments for 4 n8 groups, hi & lo
            uint32_t bh[4][2], bl[4][2];
#pragma unroll
            for (int q = 0; q < 2; ++q) {
                int brow = wn * 32 + ((2 * q + (g >> 1)) << 3) + rr;
                int bch  = 2 * s + (g & 1);
                uint32_t ad = stb + SM_BH + brow * 64 + (SWZC(brow, bch) << 4);
                uint32_t r0, r1, r2, r3;
                LDSM4(r0, r1, r2, r3, ad);
                bh[2*q][0] = r0; bh[2*q][1] = r1; bh[2*q+1][0] = r2; bh[2*q+1][1] = r3;
                ad = stb + SM_BL + brow * 64 + (SWZC(brow, bch) << 4);
                LDSM4(r0, r1, r2, r3, ad);
                bl[2*q][0] = r0; bl[2*q][1] = r1; bl[2*q+1][0] = r2; bl[2*q+1][1] = r3;
            }
#pragma unroll
            for (int mt = 0; mt < 4; ++mt) {
                int arow = wm * 64 + mt * 16 + ((g & 1) << 3) + rr;
                int ach  = 2 * s + (g >> 1);
                uint32_t aH[4], aL[4];
                uint32_t ad = stb + SM_AH + arow * 64 + (SWZC(arow, ach) << 4);
                LDSM4(aH[0], aH[1], aH[2], aH[3], ad);
                ad = stb + SM_AL + arow * 64 + (SWZC(arow, ach) << 4);
                LDSM4(aL[0], aL[1], aL[2], aL[3], ad);
#pragma unroll
                for (int nt = 0; nt < 4; ++nt) {
                    MMA16816(acc[mt][nt], aH, bh[nt]);
                    MMA16816(acc[mt][nt], aH, bl[nt]);
                    MMA16816(acc[mt][nt], aL, bh[nt]);
                }
            }
        }
    }

    // ---------------- epilogue ----------------
#pragma unroll
    for (int mt = 0; mt < 4; ++mt) {
        int r0g = row0 + wm * 64 + mt * 16 + (lane >> 2);
        int r1g = r0g + 8;
#pragma unroll
        for (int nt = 0; nt < 4; ++nt) {
            int c = col0 + wn * 32 + nt * 8 + ((lane & 3) << 1);
            float d0 = acc[mt][nt][0], d1 = acc[mt][nt][1];
            float d2 = acc[mt][nt][2], d3 = acc[mt][nt][3];
            if (MODE == MODE_SPLIT_BIAS) {
                float b0 = bias[c], b1 = bias[c + 1];
                bf16 h0, l0, h1, l1;
                split2(d0 + b0, h0, l0); split2(d1 + b1, h1, l1);
                *(uint32_t*)(Ch + (long long)r0g * ldc + c) = pack2(h0, h1);
                *(uint32_t*)(Cl + (long long)r0g * ldc + c) = pack2(l0, l1);
                split2(d2 + b0, h0, l0); split2(d3 + b1, h1, l1);
                *(uint32_t*)(Ch + (long long)r1g * ldc + c) = pack2(h0, h1);
                *(uint32_t*)(Cl + (long long)r1g * ldc + c) = pack2(l0, l1);
            } else {
                float* base = Cf + blockIdx.z * sC;
                float m = (MODE == MODE_SCALE_F32) ? scale : 1.0f;
                *(float2*)(base + (long long)r0g * ldc + c) = make_float2(d0 * m, d1 * m);
                *(float2*)(base + (long long)r1g * ldc + c) = make_float2(d2 * m, d3 * m);
            }
        }
    }
}

// ---------------- prep kernels ----------------
__global__ void split_convert(const float* __restrict__ src,
                              bf16* __restrict__ h, bf16* __restrict__ l, long long n4)
{
    long long i = (long long)blockIdx.x * blockDim.x + threadIdx.x;
    if (i >= n4) return;
    float4 t = ((const float4*)src)[i];
    bf16 h0,h1,h2,h3,l0,l1,l2,l3;
    split2(t.x,h0,l0); split2(t.y,h1,l1); split2(t.z,h2,l2); split2(t.w,h3,l3);
    *(uint2*)(h + i * 4) = make_uint2(pack2(h0,h1), pack2(h2,h3));
    *(uint2*)(l + i * 4) = make_uint2(pack2(l0,l1), pack2(l2,l3));
}

// W [768][2304] fp32 -> W^T [2304][768] bf16 hi/lo
__global__ __launch_bounds__(256)
void wtrans_kernel(const float* __restrict__ W, bf16* __restrict__ th, bf16* __restrict__ tl)
{
    __shared__ float ts[32][33];
    const int tx = threadIdx.x, ty = threadIdx.y;
    const int c0 = blockIdx.x * 32;   // along 2304
    const int r0 = blockIdx.y * 32;   // along 768
#pragma unroll
    for (int j = 0; j < 4; ++j)
        ts[ty + 8 * j][tx] = W[(long long)(r0 + ty + 8 * j) * DQKV + c0 + tx];
    __syncthreads();
#pragma unroll
    for (int j = 0; j < 4; ++j) {
        float v = ts[tx][ty + 8 * j];
        bf16 h, l; split2(v, h, l);
        long long o = (long long)(c0 + ty + 8 * j) * DMODEL + r0 + tx;
        th[o] = h; tl[o] = l;
    }
}

// V slice of qkv (cols 1536..2303) -> V^T per batch [768][2048] hi/lo
__global__ __launch_bounds__(256)
void vtrans_kernel(const bf16* __restrict__ qh, const bf16* __restrict__ ql,
                   bf16* __restrict__ vth, bf16* __restrict__ vtl)
{
    __shared__ bf16 th[32][33], tl[32][33];
    const int tx = threadIdx.x, ty = threadIdx.y;
    const int t0 = blockIdx.x * 32;   // tokens
    const int d0 = blockIdx.y * 32;   // dmodel
    const int b  = blockIdx.z;
    const long long base = (long long)b * SEQ * DQKV + 2 * DMODEL;
#pragma unroll
    for (int j = 0; j < 4; ++j) {
        long long o = base + (long long)(t0 + ty + 8 * j) * DQKV + d0 + tx;
        th[ty + 8 * j][tx] = qh[o];
        tl[ty + 8 * j][tx] = ql[o];
    }
    __syncthreads();
    const long long ob = (long long)b * DMODEL * SEQ;
#pragma unroll
    for (int j = 0; j < 4; ++j) {
        long long o = ob + (long long)(d0 + ty + 8 * j) * SEQ + t0 + tx;
        vth[o] = th[tx][ty + 8 * j];
        vtl[o] = tl[tx][ty + 8 * j];
    }
}

// softmax over 2048 cols; emit P as bf16 hi/lo
__global__ __launch_bounds__(256)
void softmax_split_kernel(const float* __restrict__ S,
                          bf16* __restrict__ Ph, bf16* __restrict__ Pl)
{
    __shared__ float red[32];
    const int tid = threadIdx.x;
    const float* p = S + (long long)blockIdx.x * SEQ;
    bf16* ph = Ph + (long long)blockIdx.x * SEQ;
    bf16* pl = Pl + (long long)blockIdx.x * SEQ;

    float v[8];
    float m = -INFINITY;
#pragma unroll
    for (int i = 0; i < 8; ++i) { v[i] = p[tid + i * 256]; m = fmaxf(m, v[i]); }
#pragma unroll
    for (int o = 16; o; o >>= 1) m = fmaxf(m, __shfl_xor_sync(0xffffffffu, m, o));
    const int warp = tid >> 5, lane = tid & 31;
    if (lane == 0) red[warp] = m;
    __syncthreads();
    if (warp == 0) {
        float t = (lane < 8) ? red[lane] : -INFINITY;
#pragma unroll
        for (int o = 4; o; o >>= 1) t = fmaxf(t, __shfl_xor_sync(0xffffffffu, t, o));
        if (lane == 0) red[0] = t;
    }
    __syncthreads();
    m = red[0];
    __syncthreads();

    float s = 0.0f;
#pragma unroll
    for (int i = 0; i < 8; ++i) { v[i] = __expf(v[i] - m); s += v[i]; }
#pragma unroll
    for (int o = 16; o; o >>= 1) s += __shfl_xor_sync(0xffffffffu, s, o);
    if (lane == 0) red[warp] = s;
    __syncthreads();
    if (warp == 0) {
        float t = (lane < 8) ? red[lane] : 0.0f;
#pragma unroll
        for (int o = 4; o; o >>= 1) t += __shfl_xor_sync(0xffffffffu, t, o);
        if (lane == 0) red[0] = t;
    }
    __syncthreads();
    const float inv = 1.0f / red[0];
#pragma unroll
    for (int i = 0; i < 8; ++i) {
        bf16 h, l; split2(v[i] * inv, h, l);
        ph[tid + i * 256] = h;
        pl[tid + i * 256] = l;
    }
}

// ---------------- launch ----------------
extern "C" void kernel_launch(void* const* d_in, const int* in_sizes, int n_in,
                              void* d_out, int out_size)
{
    const float* x = (const float*)d_in[0];
    const float* W = (const float*)d_in[1];
    const float* b = (const float*)d_in[2];
    float* out = (float*)d_out;

    bf16 *xh, *xl, *wth, *wtl, *qh, *ql, *ph, *pl, *vth, *vtl;
    float *scores;
    cudaGetSymbolAddress((void**)&xh, g_xh);   cudaGetSymbolAddress((void**)&xl, g_xl);
    cudaGetSymbolAddress((void**)&wth, g_wth); cudaGetSymbolAddress((void**)&wtl, g_wtl);
    cudaGetSymbolAddress((void**)&qh, g_qh);   cudaGetSymbolAddress((void**)&ql, g_ql);
    cudaGetSymbolAddress((void**)&ph, g_ph);   cudaGetSymbolAddress((void**)&pl, g_pl);
    cudaGetSymbolAddress((void**)&vth, g_vth); cudaGetSymbolAddress((void**)&vtl, g_vtl);
    cudaGetSymbolAddress((void**)&scores, g_scores);

    cudaFuncSetAttribute(gemm_mma<MODE_SPLIT_BIAS>, cudaFuncAttributeMaxDynamicSharedMemorySize, SM_TOTAL);
    cudaFuncSetAttribute(gemm_mma<MODE_SCALE_F32>,  cudaFuncAttributeMaxDynamicSharedMemorySize, SM_TOTAL);
    cudaFuncSetAttribute(gemm_mma<MODE_F32>,        cudaFuncAttributeMaxDynamicSharedMemorySize, SM_TOTAL);

    const float scale = 1.0f / sqrtf((float)DMODEL);

    // prep
    {
        long long n4 = (long long)MROWS * DMODEL / 4;
        split_convert<<<(unsigned)((n4 + 255) / 256), 256>>>(x, xh, xl, n4);
        wtrans_kernel<<<dim3(DQKV / 32, DMODEL / 32), dim3(32, 8)>>>(W, wth, wtl);
    }

    // GEMM1: qkv = x @ W + b -> qh/ql   M=16384, N=2304, K=768
    gemm_mma<MODE_SPLIT_BIAS><<<dim3(DQKV / BN, MROWS / BM, 1), 256, SM_TOTAL>>>(
        xh, xl, wth, wtl, nullptr, qh, ql, b,
        DMODEL, DMODEL, DMODEL, DQKV, 0LL, 0LL, 0LL, 1.0f);

    // V^T
    vtrans_kernel<<<dim3(SEQ / 32, DMODEL / 32, BATCH), dim3(32, 8)>>>(qh, ql, vth, vtl);

    // GEMM2: S = Q K^T * scale   per batch M=N=2048, K=768
    gemm_mma<MODE_SCALE_F32><<<dim3(SEQ / BN, SEQ / BM, BATCH), 256, SM_TOTAL>>>(
        qh, ql, qh + DMODEL, ql + DMODEL, scores, nullptr, nullptr, nullptr,
        DMODEL, DQKV, DQKV, SEQ,
        (long long)SEQ * DQKV, (long long)SEQ * DQKV, (long long)SEQ * SEQ, scale);

    // softmax -> P hi/lo
    softmax_split_kernel<<<BATCH * SEQ, 256>>>(scores, ph, pl);

    // GEMM3: out = P @ V (V^T K-major)  per batch M=2048, N=768, K=2048
    gemm_mma<MODE_F32><<<dim3(DMODEL / BN, SEQ / BM, BATCH), 256, SM_TOTAL>>>(
        ph, pl, vth, vtl, out, nullptr, nullptr, nullptr,
        SEQ, SEQ, SEQ, DMODEL,
        (long long)SEQ * SEQ, (long long)DMODEL * SEQ, (long long)SEQ * DMODEL, 1.0f);
}

// round 7
// speedup vs baseline: 2.7853x; 1.2220x over previous
#include <cuda_runtime.h>
#include <cuda_bf16.h>
#include <math.h>
#include <stdint.h>

// ----------------------------------------------------------------------------
// SelfAttention B=8, N=2048, D=768 — mma.sync bf16 (fp32 acc), 3-term split
// emulation (AhBh + AhBl + AlBh). CTA tile 128x256, warp tile 64x64
// (MMA:LDSM 6:1). 2-stage cp.async pipeline, 96 KB smem (proven footprint).
// ----------------------------------------------------------------------------

#define BATCH   8
#define SEQ     2048
#define DMODEL  768
#define DQKV    2304
#define MROWS   (BATCH * SEQ)

typedef __nv_bfloat16 bf16;

__device__ bf16  g_xh[(long long)MROWS * DMODEL];
__device__ bf16  g_xl[(long long)MROWS * DMODEL];
__device__ bf16  g_wth[(long long)DQKV * DMODEL];        // W^T K-major [2304][768]
__device__ bf16  g_wtl[(long long)DQKV * DMODEL];
__device__ bf16  g_qh[(long long)MROWS * DQKV];
__device__ bf16  g_ql[(long long)MROWS * DQKV];
__device__ float g_scores[(long long)BATCH * SEQ * SEQ];
__device__ bf16  g_ph[(long long)BATCH * SEQ * SEQ];
__device__ bf16  g_pl[(long long)BATCH * SEQ * SEQ];
__device__ bf16  g_vth[(long long)BATCH * DMODEL * SEQ]; // V^T per batch [768][2048]
__device__ bf16  g_vtl[(long long)BATCH * DMODEL * SEQ];

// ------------------------- helpers -------------------------
__device__ __forceinline__ uint32_t smem_u32(const void* p) {
    uint32_t a;
    asm("{ .reg .u64 t; cvta.to.shared.u64 t, %1; cvt.u32.u64 %0, t; }"
        : "=r"(a) : "l"(p));
    return a;
}
__device__ __forceinline__ void split2(float x, bf16& h, bf16& l) {
    h = __float2bfloat16(x);
    l = __float2bfloat16(x - __bfloat162float(h));
}
__device__ __forceinline__ uint32_t pack2(bf16 a, bf16 b) {
    __nv_bfloat162 v(a, b);
    return *reinterpret_cast<uint32_t*>(&v);
}

#define CPA16(dst, src) \
    asm volatile("cp.async.cg.shared.global [%0], [%1], 16;" :: "r"(dst), "l"(src))
#define CPA_COMMIT() asm volatile("cp.async.commit_group;" ::: "memory")
#define CPA_WAIT1()  asm volatile("cp.async.wait_group 1;" ::: "memory")

#define LDSM4(r0, r1, r2, r3, addr) \
    asm volatile("ldmatrix.sync.aligned.m8n8.x4.shared.b16 {%0,%1,%2,%3}, [%4];" \
                 : "=r"(r0), "=r"(r1), "=r"(r2), "=r"(r3) : "r"(addr))

#define MMA16816(d, a, b) \
    asm volatile("mma.sync.aligned.m16n8k16.row.col.f32.bf16.bf16.f32 " \
                 "{%0,%1,%2,%3}, {%4,%5,%6,%7}, {%8,%9}, {%0,%1,%2,%3};" \
                 : "+f"((d)[0]), "+f"((d)[1]), "+f"((d)[2]), "+f"((d)[3]) \
                 : "r"((a)[0]), "r"((a)[1]), "r"((a)[2]), "r"((a)[3]), \
                   "r"((b)[0]), "r"((b)[1]))

// 64B rows, 4x16B chunks; conflict-free across 8-row ldmatrix phases
#define SWZC(r, c) ((c) ^ (((r) ^ ((r) >> 2)) & 3))

// ------------------------- GEMM config -------------------------
#define BM 128
#define BN 256
#define BKE 32            // bf16 k per chunk (64 B per row)
#define STAGES 2
#define SM_AH 0            // 128*64 = 8 KB
#define SM_AL 8192
#define SM_BH 16384        // 256*64 = 16 KB
#define SM_BL 32768
#define SM_STAGE 49152     // 48 KB
#define SM_TOTAL (STAGES * SM_STAGE)   // 98304 (same footprint that passed in R4)

#define MODE_SPLIT_BIAS 0
#define MODE_SCALE_F32  1
#define MODE_F32        2

template<int MODE>
__global__ __launch_bounds__(256, 1)
void gemm_mma(const bf16* __restrict__ Ah, const bf16* __restrict__ Al,
              const bf16* __restrict__ Bh, const bf16* __restrict__ Bl,
              float* __restrict__ Cf, bf16* __restrict__ Ch, bf16* __restrict__ Cl,
              const float* __restrict__ bias,
              int K, int lda, int ldb, int ldc,
              long long sA, long long sB, long long sC, float scale)
{
    extern __shared__ char smem[];
    const uint32_t sm = smem_u32(smem);
    const int tid  = threadIdx.x;
    const int wid  = tid >> 5;
    const int lane = tid & 31;
    const int wm   = wid & 1;        // 2 warps along M (64 rows)
    const int wn   = wid >> 1;       // 4 warps along N (64 cols)
    const int row0 = blockIdx.y * BM;
    const int col0 = blockIdx.x * BN;

    const long long ldaB = (long long)lda * 2;
    const long long ldbB = (long long)ldb * 2;
    const char* pAh = (const char*)(Ah + blockIdx.z * sA + (long long)row0 * lda);
    const char* pAl = (const char*)(Al + blockIdx.z * sA + (long long)row0 * lda);
    const char* pBh = (const char*)(Bh + blockIdx.z * sB + (long long)col0 * ldb);
    const char* pBl = (const char*)(Bl + blockIdx.z * sB + (long long)col0 * ldb);

    float acc[4][8][4];
#pragma unroll
    for (int i = 0; i < 4; ++i)
#pragma unroll
        for (int j = 0; j < 8; ++j)
#pragma unroll
            for (int t = 0; t < 4; ++t) acc[i][j][t] = 0.0f;

    const int NC = K / BKE;

    auto load_chunk = [&](int ch) {
        const uint32_t stb = sm + (ch & 1) * SM_STAGE;
        const long long kb = (long long)ch * 64;
#pragma unroll
        for (int i = 0; i < 2; ++i) {
            int u = i * 256 + tid;
            int r = u >> 2, c = u & 3;
            uint32_t dsw = (uint32_t)(r * 64 + (SWZC(r, c) << 4));
            long long go = (long long)r * ldaB + kb + c * 16;
            CPA16(stb + SM_AH + dsw, pAh + go);
            CPA16(stb + SM_AL + dsw, pAl + go);
        }
#pragma unroll
        for (int i = 0; i < 4; ++i) {
            int u = i * 256 + tid;
            int r = u >> 2, c = u & 3;
            uint32_t dsw = (uint32_t)(r * 64 + (SWZC(r, c) << 4));
            long long go = (long long)r * ldbB + kb + c * 16;
            CPA16(stb + SM_BH + dsw, pBh + go);
            CPA16(stb + SM_BL + dsw, pBl + go);
        }
    };

    load_chunk(0); CPA_COMMIT();

    const int g  = lane >> 3;
    const int rr = lane & 7;

    for (int ch = 0; ch < NC; ++ch) {
        // prefetch next chunk into the other buffer (readers of that buffer
        // finished at the trailing __syncthreads of the previous iteration)
        if (ch + 1 < NC) load_chunk(ch + 1);
        CPA_COMMIT();
        CPA_WAIT1();          // chunk ch resident (newest group may be pending)
        __syncthreads();

        const uint32_t stb = sm + (ch & 1) * SM_STAGE;
#pragma unroll
        for (int s = 0; s < 2; ++s) {
            uint32_t bh[8][2], bl[8][2];
#pragma unroll
            for (int q = 0; q < 4; ++q) {
                int brow = wn * 64 + ((2 * q + (g >> 1)) << 3) + rr;
                int bch  = 2 * s + (g & 1);
                uint32_t r0, r1, r2, r3;
                uint32_t ad = stb + SM_BH + brow * 64 + (SWZC(brow, bch) << 4);
                LDSM4(r0, r1, r2, r3, ad);
                bh[2*q][0] = r0; bh[2*q][1] = r1; bh[2*q+1][0] = r2; bh[2*q+1][1] = r3;
                ad = stb + SM_BL + brow * 64 + (SWZC(brow, bch) << 4);
                LDSM4(r0, r1, r2, r3, ad);
                bl[2*q][0] = r0; bl[2*q][1] = r1; bl[2*q+1][0] = r2; bl[2*q+1][1] = r3;
            }
#pragma unroll
            for (int mt = 0; mt < 4; ++mt) {
                int arow = wm * 64 + mt * 16 + ((g & 1) << 3) + rr;
                int ach  = 2 * s + (g >> 1);
                uint32_t aH[4], aL[4];
                uint32_t ad = stb + SM_AH + arow * 64 + (SWZC(arow, ach) << 4);
                LDSM4(aH[0], aH[1], aH[2], aH[3], ad);
                ad = stb + SM_AL + arow * 64 + (SWZC(arow, ach) << 4);
                LDSM4(aL[0], aL[1], aL[2], aL[3], ad);
#pragma unroll
                for (int nt = 0; nt < 8; ++nt) {
                    MMA16816(acc[mt][nt], aH, bh[nt]);
                    MMA16816(acc[mt][nt], aH, bl[nt]);
                    MMA16816(acc[mt][nt], aL, bh[nt]);
                }
            }
        }
        __syncthreads();      // all readers done before next iter overwrites
    }

    // ---------------- epilogue ----------------
#pragma unroll
    for (int mt = 0; mt < 4; ++mt) {
        int r0g = row0 + wm * 64 + mt * 16 + (lane >> 2);
        int r1g = r0g + 8;
#pragma unroll
        for (int nt = 0; nt < 8; ++nt) {
            int c = col0 + wn * 64 + nt * 8 + ((lane & 3) << 1);
            float d0 = acc[mt][nt][0], d1 = acc[mt][nt][1];
            float d2 = acc[mt][nt][2], d3 = acc[mt][nt][3];
            if (MODE == MODE_SPLIT_BIAS) {
                float b0 = bias[c], b1 = bias[c + 1];
                bf16 h0, l0, h1, l1;
                split2(d0 + b0, h0, l0); split2(d1 + b1, h1, l1);
                *(uint32_t*)(Ch + (long long)r0g * ldc + c) = pack2(h0, h1);
                *(uint32_t*)(Cl + (long long)r0g * ldc + c) = pack2(l0, l1);
                split2(d2 + b0, h0, l0); split2(d3 + b1, h1, l1);
                *(uint32_t*)(Ch + (long long)r1g * ldc + c) = pack2(h0, h1);
                *(uint32_t*)(Cl + (long long)r1g * ldc + c) = pack2(l0, l1);
            } else {
                float* base = Cf + blockIdx.z * sC;
                float m = (MODE == MODE_SCALE_F32) ? scale : 1.0f;
                *(float2*)(base + (long long)r0g * ldc + c) = make_float2(d0 * m, d1 * m);
                *(float2*)(base + (long long)r1g * ldc + c) = make_float2(d2 * m, d3 * m);
            }
        }
    }
}

// ---------------- prep kernels ----------------
__global__ void split_convert(const float* __restrict__ src,
                              bf16* __restrict__ h, bf16* __restrict__ l, long long n4)
{
    long long i = (long long)blockIdx.x * blockDim.x + threadIdx.x;
    if (i >= n4) return;
    float4 t = ((const float4*)src)[i];
    bf16 h0,h1,h2,h3,l0,l1,l2,l3;
    split2(t.x,h0,l0); split2(t.y,h1,l1); split2(t.z,h2,l2); split2(t.w,h3,l3);
    *(uint2*)(h + i * 4) = make_uint2(pack2(h0,h1), pack2(h2,h3));
    *(uint2*)(l + i * 4) = make_uint2(pack2(l0,l1), pack2(l2,l3));
}

// W [768][2304] fp32 -> W^T [2304][768] bf16 hi/lo
__global__ __launch_bounds__(256)
void wtrans_kernel(const float* __restrict__ W, bf16* __restrict__ th, bf16* __restrict__ tl)
{
    __shared__ float ts[32][33];
    const int tx = threadIdx.x, ty = threadIdx.y;
    const int c0 = blockIdx.x * 32;
    const int r0 = blockIdx.y * 32;
#pragma unroll
    for (int j = 0; j < 4; ++j)
        ts[ty + 8 * j][tx] = W[(long long)(r0 + ty + 8 * j) * DQKV + c0 + tx];
    __syncthreads();
#pragma unroll
    for (int j = 0; j < 4; ++j) {
        float v = ts[tx][ty + 8 * j];
        bf16 h, l; split2(v, h, l);
        long long o = (long long)(c0 + ty + 8 * j) * DMODEL + r0 + tx;
        th[o] = h; tl[o] = l;
    }
}

// V slice of qkv (cols 1536..2303) -> V^T per batch [768][2048] hi/lo
__global__ __launch_bounds__(256)
void vtrans_kernel(const bf16* __restrict__ qh, const bf16* __restrict__ ql,
                   bf16* __restrict__ vth, bf16* __restrict__ vtl)
{
    __shared__ bf16 th[32][33], tl[32][33];
    const int tx = threadIdx.x, ty = threadIdx.y;
    const int t0 = blockIdx.x * 32;
    const int d0 = blockIdx.y * 32;
    const int b  = blockIdx.z;
    const long long base = (long long)b * SEQ * DQKV + 2 * DMODEL;
#pragma unroll
    for (int j = 0; j < 4; ++j) {
        long long o = base + (long long)(t0 + ty + 8 * j) * DQKV + d0 + tx;
        th[ty + 8 * j][tx] = qh[o];
        tl[ty + 8 * j][tx] = ql[o];
    }
    __syncthreads();
    const long long ob = (long long)b * DMODEL * SEQ;
#pragma unroll
    for (int j = 0; j < 4; ++j) {
        long long o = ob + (long long)(d0 + ty + 8 * j) * SEQ + t0 + tx;
        vth[o] = th[tx][ty + 8 * j];
        vtl[o] = tl[tx][ty + 8 * j];
    }
}

// softmax over 2048 cols; emit P as bf16 hi/lo
__global__ __launch_bounds__(256)
void softmax_split_kernel(const float* __restrict__ S,
                          bf16* __restrict__ Ph, bf16* __restrict__ Pl)
{
    __shared__ float red[32];
    const int tid = threadIdx.x;
    const float* p = S + (long long)blockIdx.x * SEQ;
    bf16* ph = Ph + (long long)blockIdx.x * SEQ;
    bf16* pl = Pl + (long long)blockIdx.x * SEQ;

    float v[8];
    float m = -INFINITY;
#pragma unroll
    for (int i = 0; i < 8; ++i) { v[i] = p[tid + i * 256]; m = fmaxf(m, v[i]); }
#pragma unroll
    for (int o = 16; o; o >>= 1) m = fmaxf(m, __shfl_xor_sync(0xffffffffu, m, o));
    const int warp = tid >> 5, lane = tid & 31;
    if (lane == 0) red[warp] = m;
    __syncthreads();
    if (warp == 0) {
        float t = (lane < 8) ? red[lane] : -INFINITY;
#pragma unroll
        for (int o = 4; o; o >>= 1) t = fmaxf(t, __shfl_xor_sync(0xffffffffu, t, o));
        if (lane == 0) red[0] = t;
    }
    __syncthreads();
    m = red[0];
    __syncthreads();

    float s = 0.0f;
#pragma unroll
    for (int i = 0; i < 8; ++i) { v[i] = __expf(v[i] - m); s += v[i]; }
#pragma unroll
    for (int o = 16; o; o >>= 1) s += __shfl_xor_sync(0xffffffffu, s, o);
    if (lane == 0) red[warp] = s;
    __syncthreads();
    if (warp == 0) {
        float t = (lane < 8) ? red[lane] : 0.0f;
#pragma unroll
        for (int o = 4; o; o >>= 1) t += __shfl_xor_sync(0xffffffffu, t, o);
        if (lane == 0) red[0] = t;
    }
    __syncthreads();
    const float inv = 1.0f / red[0];
#pragma unroll
    for (int i = 0; i < 8; ++i) {
        bf16 h, l; split2(v[i] * inv, h, l);
        ph[tid + i * 256] = h;
        pl[tid + i * 256] = l;
    }
}

// ---------------- launch ----------------
extern "C" void kernel_launch(void* const* d_in, const int* in_sizes, int n_in,
                              void* d_out, int out_size)
{
    const float* x = (const float*)d_in[0];
    const float* W = (const float*)d_in[1];
    const float* b = (const float*)d_in[2];
    float* out = (float*)d_out;

    bf16 *xh, *xl, *wth, *wtl, *qh, *ql, *ph, *pl, *vth, *vtl;
    float *scores;
    cudaGetSymbolAddress((void**)&xh, g_xh);   cudaGetSymbolAddress((void**)&xl, g_xl);
    cudaGetSymbolAddress((void**)&wth, g_wth); cudaGetSymbolAddress((void**)&wtl, g_wtl);
    cudaGetSymbolAddress((void**)&qh, g_qh);   cudaGetSymbolAddress((void**)&ql, g_ql);
    cudaGetSymbolAddress((void**)&ph, g_ph);   cudaGetSymbolAddress((void**)&pl, g_pl);
    cudaGetSymbolAddress((void**)&vth, g_vth); cudaGetSymbolAddress((void**)&vtl, g_vtl);
    cudaGetSymbolAddress((void**)&scores, g_scores);

    cudaFuncSetAttribute(gemm_mma<MODE_SPLIT_BIAS>, cudaFuncAttributeMaxDynamicSharedMemorySize, SM_TOTAL);
    cudaFuncSetAttribute(gemm_mma<MODE_SCALE_F32>,  cudaFuncAttributeMaxDynamicSharedMemorySize, SM_TOTAL);
    cudaFuncSetAttribute(gemm_mma<MODE_F32>,        cudaFuncAttributeMaxDynamicSharedMemorySize, SM_TOTAL);

    const float scale = 1.0f / sqrtf((float)DMODEL);

    // prep
    {
        long long n4 = (long long)MROWS * DMODEL / 4;
        split_convert<<<(unsigned)((n4 + 255) / 256), 256>>>(x, xh, xl, n4);
        wtrans_kernel<<<dim3(DQKV / 32, DMODEL / 32), dim3(32, 8)>>>(W, wth, wtl);
    }

    // GEMM1: qkv = x @ W + b -> qh/ql   M=16384, N=2304, K=768
    gemm_mma<MODE_SPLIT_BIAS><<<dim3(DQKV / BN, MROWS / BM, 1), 256, SM_TOTAL>>>(
        xh, xl, wth, wtl, nullptr, qh, ql, b,
        DMODEL, DMODEL, DMODEL, DQKV, 0LL, 0LL, 0LL, 1.0f);

    // V^T
    vtrans_kernel<<<dim3(SEQ / 32, DMODEL / 32, BATCH), dim3(32, 8)>>>(qh, ql, vth, vtl);

    // GEMM2: S = Q K^T * scale   per batch M=N=2048, K=768
    gemm_mma<MODE_SCALE_F32><<<dim3(SEQ / BN, SEQ / BM, BATCH), 256, SM_TOTAL>>>(
        qh, ql, qh + DMODEL, ql + DMODEL, scores, nullptr, nullptr, nullptr,
        DMODEL, DQKV, DQKV, SEQ,
        (long long)SEQ * DQKV, (long long)SEQ * DQKV, (long long)SEQ * SEQ, scale);

    // softmax -> P hi/lo
    softmax_split_kernel<<<BATCH * SEQ, 256>>>(scores, ph, pl);

    // GEMM3: out = P @ V (V^T K-major)  per batch M=2048, N=768, K=2048
    gemm_mma<MODE_F32><<<dim3(DMODEL / BN, SEQ / BM, BATCH), 256, SM_TOTAL>>>(
        ph, pl, vth, vtl, out, nullptr, nullptr, nullptr,
        SEQ, SEQ, SEQ, DMODEL,
        (long long)SEQ * SEQ, (long long)DMODEL * SEQ, (long long)SEQ * DMODEL, 1.0f);
}